// round 15
// baseline (speedup 1.0000x reference)
#include <cuda_runtime.h>
#include <cuda_fp16.h>

// Problem constants (fixed by the dataset)
#define D   64
#define P   3
#define H   128
#define O   128
#define NMAX   100000
#define NCMAX  50000
#define EMAX   1600000
#define TILE   64

// ---------------- scratch (device globals; no allocation allowed) ----------
__device__ __half       g_Ah[NMAX * H];      // per-source layer-1 partial (+b1), fp16
__device__ __half       g_Bh[NCMAX * H];     // per-center layer-1 partial, fp16
__device__ int          g_rowptr[NCMAX + 1];
__device__ int          g_cursor[NCMAX];
__device__ int2         g_edge[EMAX];        // CSR-sorted (src, dst)
__device__ unsigned int g_enc[NCMAX * O];    // offset-encoded running max (0 = empty)
__device__ int          g_blocksum[64];      // scan partials
__device__ int          g_sflag[64];         // scan lookback flags

// ======================= helpers ===========================================
__device__ __forceinline__ unsigned smem_u32(const void* p) {
    unsigned a;
    asm("{ .reg .u64 t; cvta.to.shared.u64 t, %1; cvt.u32.u64 %0, t; }"
        : "=r"(a) : "l"(p));
    return a;
}
// order-preserving float->uint
__device__ __forceinline__ unsigned fenc(float f) {
    unsigned u = __float_as_uint(f);
    return (u & 0x80000000u) ? ~u : (u | 0x80000000u);
}
__device__ __forceinline__ float fdec(unsigned u) {
    return __uint_as_float((u & 0x80000000u) ? (u & 0x7fffffffu) : ~u);
}
// offset so that "empty" == 0 (g_enc is kept all-zero between launches)
#define ENC_OFF 0x007FFFFFu

__device__ __forceinline__ unsigned pack_h2(float lo, float hi) {
    unsigned u;
    asm("cvt.rn.f16x2.f32 %0, %1, %2;" : "=r"(u) : "f"(hi), "f"(lo));
    return u;
}
// relu(a - b) on packed half2
__device__ __forceinline__ unsigned srelu(unsigned au, unsigned bu) {
    __half2 a = *reinterpret_cast<__half2*>(&au);
    __half2 b = *reinterpret_cast<__half2*>(&bu);
    __half2 r = __hmax2(__hsub2(a, b), __float2half2_rn(0.0f));
    return *reinterpret_cast<unsigned*>(&r);
}
__device__ __forceinline__ void ldsm4(unsigned& r0, unsigned& r1,
                                      unsigned& r2, unsigned& r3, unsigned addr)
{
    asm volatile("ldmatrix.sync.aligned.m8n8.x4.shared.b16 {%0,%1,%2,%3}, [%4];"
                 : "=r"(r0), "=r"(r1), "=r"(r2), "=r"(r3) : "r"(addr));
}
__device__ __forceinline__ void mma_f16(float* d, const unsigned* a,
                                        unsigned b0, unsigned b1)
{
    asm volatile("mma.sync.aligned.m16n8k16.row.col.f32.f16.f16.f32 "
                 "{%0,%1,%2,%3}, {%4,%5,%6,%7}, {%8,%9}, {%0,%1,%2,%3};"
                 : "+f"(d[0]), "+f"(d[1]), "+f"(d[2]), "+f"(d[3])
                 : "r"(a[0]), "r"(a[1]), "r"(a[2]), "r"(a[3]),
                   "r"(b0), "r"(b1));
}

// ---------------------------------------------------------------------------
// k_zero: cursor + scan flags (g_enc maintained zero by k_decode)
// ---------------------------------------------------------------------------
__global__ void k_zero(int NC)
{
    const int i = blockIdx.x * 1024 + threadIdx.x;
    if (i < 64) { g_sflag[i] = 0; g_blocksum[i] = 0; }
    if (i < NC) g_cursor[i] = 0;
}

// ---------------------------------------------------------------------------
// k_pre (fused): block ranges
//   [0, nA)       : A = x@W1[:64] (fp16 MMA) + pos@W1row + b1 -> g_Ah
//   [nA, nA+nB)   : B rows -> g_Bh
//   [nA+nB, +nH)  : histogram of dst into g_cursor
// ---------------------------------------------------------------------------
#define XSTR 144                 // smem row stride bytes (odd multiple of 16)

__global__ void __launch_bounds__(256, 2)
k_pre(const float* __restrict__ x, const float* __restrict__ pos,
      const float* __restrict__ pos_c, const float* __restrict__ W1,
      const float* __restrict__ b1, const int* __restrict__ dst,
      int N, int NC, int E, int nA, int nB, int nH)
{
    const int t = threadIdx.x;
    const int bid = blockIdx.x;

    if (bid >= nA + nB) {               // histogram
        const int i0 = (bid - nA - nB) * 256 + t;
        const int stride = nH * 256;
        for (int e = i0; e < E; e += stride) atomicAdd(&g_cursor[dst[e]], 1);
        return;
    }
    if (bid >= nA) {                    // B rows
        const int bb = bid - nA;
#pragma unroll
        for (int r = 0; r < 8; r++) {
            const int idx = bb * 2048 + r * 256 + t;
            if (idx < NC * H) {
                const int c = idx >> 7;
                const int h = idx & 127;
                const float v = pos_c[c * 3 + 0] * W1[(D + 0) * H + h]
                              + pos_c[c * 3 + 1] * W1[(D + 1) * H + h]
                              + pos_c[c * 3 + 2] * W1[(D + 2) * H + h];
                g_Bh[idx] = __float2half_rn(v);
            }
        }
        return;
    }

    // ---- A-GEMM block ----
    __shared__ char xs_raw[128 * XSTR];     // x tile, fp16 [128 rows][64 k]
    __shared__ char w1_raw[128 * XSTR];     // W1^T,  fp16 [128 j][64 k]
    __shared__ float posS[128][4];
    __shared__ float w1r[3][128];
    __shared__ float b1s[128];

    const int lane = t & 31, wid = t >> 5;
    const int rbase = bid * 128;

    {
        const int r = t >> 1, kh = t & 1;
        const int row = rbase + r;
        char* rp = xs_raw + r * XSTR + kh * 64;
        if (row < N) {
            const float4* xp = (const float4*)(x + (size_t)row * D + kh * 32);
#pragma unroll
            for (int i = 0; i < 4; i++) {
                const float4 v0 = xp[2 * i];
                const float4 v1 = xp[2 * i + 1];
                *(uint4*)(rp + i * 16) = make_uint4(
                    pack_h2(v0.x, v0.y), pack_h2(v0.z, v0.w),
                    pack_h2(v1.x, v1.y), pack_h2(v1.z, v1.w));
            }
        } else {
#pragma unroll
            for (int i = 0; i < 4; i++)
                *(uint4*)(rp + i * 16) = make_uint4(0, 0, 0, 0);
        }
    }
    {
        const int j = t >> 1, kh = t & 1;
        char* rp = w1_raw + j * XSTR + kh * 64;
#pragma unroll
        for (int i = 0; i < 4; i++) {
            const int k0 = kh * 32 + i * 8;
            unsigned u[4];
#pragma unroll
            for (int m = 0; m < 4; m++)
                u[m] = pack_h2(W1[(k0 + 2 * m) * H + j],
                               W1[(k0 + 2 * m + 1) * H + j]);
            *(uint4*)(rp + i * 16) = make_uint4(u[0], u[1], u[2], u[3]);
        }
    }
    if (t < 128) {
        const int row = rbase + t;
#pragma unroll
        for (int p = 0; p < P; p++) {
            posS[t][p] = (row < N) ? pos[(size_t)row * P + p] : 0.0f;
            w1r[p][t] = W1[(D + p) * H + t];
        }
        b1s[t] = b1[t];
    }
    __syncthreads();

    const int mw = wid & 3, nw = wid >> 2;
    const unsigned a_base = smem_u32(xs_raw) +
        (unsigned)((32 * mw + (lane & 7) + 8 * ((lane >> 3) & 1)) * XSTR) +
        (unsigned)((lane >> 4) * 16);
    const unsigned b_base = smem_u32(w1_raw) +
        (unsigned)((64 * nw + (lane & 7) + 8 * (lane >> 4)) * XSTR) +
        (unsigned)(((lane >> 3) & 1) * 16);

    float acc[2][8][4];
#pragma unroll
    for (int f = 0; f < 2; f++)
#pragma unroll
        for (int nb = 0; nb < 8; nb++)
#pragma unroll
            for (int r = 0; r < 4; r++) acc[f][nb][r] = 0.0f;

#pragma unroll
    for (int ks = 0; ks < 4; ks++) {
        const unsigned off = (unsigned)(ks * 32);
        unsigned af0[4], af1[4];
        ldsm4(af0[0], af0[1], af0[2], af0[3], a_base + off);
        ldsm4(af1[0], af1[1], af1[2], af1[3], a_base + 16u * XSTR + off);
#pragma unroll
        for (int q = 0; q < 4; q++) {
            unsigned bp[4];
            ldsm4(bp[0], bp[1], bp[2], bp[3],
                  b_base + (unsigned)(q * 16 * XSTR) + off);
            mma_f16(acc[0][2 * q],     af0, bp[0], bp[1]);
            mma_f16(acc[0][2 * q + 1], af0, bp[2], bp[3]);
            mma_f16(acc[1][2 * q],     af1, bp[0], bp[1]);
            mma_f16(acc[1][2 * q + 1], af1, bp[2], bp[3]);
        }
    }

    const int r0 = 32 * mw + (lane >> 2);
    const int c0 = 64 * nw + 2 * (lane & 3);
#pragma unroll
    for (int nb = 0; nb < 8; nb++) {
        const int c = c0 + 8 * nb;
        const float wc00 = w1r[0][c], wc01 = w1r[1][c], wc02 = w1r[2][c];
        const float wc10 = w1r[0][c + 1], wc11 = w1r[1][c + 1], wc12 = w1r[2][c + 1];
        const float bb0 = b1s[c], bb1 = b1s[c + 1];
#pragma unroll
        for (int f = 0; f < 2; f++) {
            const int rA = r0 + 16 * f;
            const int rB = rA + 8;
            const float d0 = acc[f][nb][0] + bb0 +
                posS[rA][0] * wc00 + posS[rA][1] * wc01 + posS[rA][2] * wc02;
            const float d1 = acc[f][nb][1] + bb1 +
                posS[rA][0] * wc10 + posS[rA][1] * wc11 + posS[rA][2] * wc12;
            const float d2 = acc[f][nb][2] + bb0 +
                posS[rB][0] * wc00 + posS[rB][1] * wc01 + posS[rB][2] * wc02;
            const float d3 = acc[f][nb][3] + bb1 +
                posS[rB][0] * wc10 + posS[rB][1] * wc11 + posS[rB][2] * wc12;
            if (rbase + rA < N)
                *(unsigned*)((char*)g_Ah + ((size_t)(rbase + rA) * H + c) * 2) =
                    pack_h2(d0, d1);
            if (rbase + rB < N)
                *(unsigned*)((char*)g_Ah + ((size_t)(rbase + rB) * H + c) * 2) =
                    pack_h2(d2, d3);
        }
    }
}

// ---------------------------------------------------------------------------
// k_scan: single-pass exclusive scan with decoupled lookback.
// grid = nblk (<=49) blocks of 1024; all resident in one wave, each block
// waits only on predecessors -> no deadlock. Flags zeroed by k_zero.
// ---------------------------------------------------------------------------
__global__ void k_scan(int nblk, int NC)
{
    __shared__ int wsum[32];
    __shared__ int s_off;
    const int tid = threadIdx.x, lane = tid & 31, w = tid >> 5;
    const int bid = blockIdx.x;
    const int i = bid * 1024 + tid;
    const int v = (i < NC) ? g_cursor[i] : 0;
    int inc = v;
#pragma unroll
    for (int o = 1; o < 32; o <<= 1) {
        const int n = __shfl_up_sync(0xFFFFFFFFu, inc, o);
        if (lane >= o) inc += n;
    }
    if (lane == 31) wsum[w] = inc;
    __syncthreads();
    if (w == 0) {
        int xv = wsum[lane];
#pragma unroll
        for (int o = 1; o < 32; o <<= 1) {
            const int n = __shfl_up_sync(0xFFFFFFFFu, xv, o);
            if (lane >= o) xv += n;
        }
        wsum[lane] = xv;
    }
    __syncthreads();
    const int total = wsum[31];

    if (tid == 0) {
        g_blocksum[bid] = total;
        __threadfence();
        atomicExch(&g_sflag[bid], 1);
    }
    // lookback: warp 0 collects predecessor partials
    if (w == 0) {
        int sum = 0;
        if (lane < bid) {
            while (atomicAdd(&g_sflag[lane], 0) == 0) {}
            sum = atomicAdd(&g_blocksum[lane], 0);
        }
        if (lane + 32 < bid) {
            while (atomicAdd(&g_sflag[lane + 32], 0) == 0) {}
            sum += atomicAdd(&g_blocksum[lane + 32], 0);
        }
#pragma unroll
        for (int o = 16; o > 0; o >>= 1)
            sum += __shfl_xor_sync(0xFFFFFFFFu, sum, o);
        if (lane == 0) s_off = sum;
    }
    __syncthreads();

    const int excl = (w ? wsum[w - 1] : 0) + inc - v + s_off;
    if (i < NC) {
        g_rowptr[i] = excl;
        g_cursor[i] = excl;
    }
    if (bid == nblk - 1 && tid == 1023) g_rowptr[NC] = s_off + total;
}

__global__ void k_scatter(const int* __restrict__ src,
                          const int* __restrict__ dst, int E)
{
    const int i = blockIdx.x * blockDim.x + threadIdx.x;
    if (i < E) {
        const int d = dst[i];
        const int p = atomicAdd(&g_cursor[d], 1);
        g_edge[p] = make_int2(src[i], d);
    }
}

// ---------------------------------------------------------------------------
// Aggregate: TILE=64, 256 threads, 2 CTAs/SM (grid 304 = 2 x 152 SMs).
// Static interleaved tile assignment. Double-buffered h1; prefetch tile+G
// LDGs held in regs across MMA. Offset encoding (empty == 0).
// (Byte-identical structure to the 409.7us R14 kernel.)
// ---------------------------------------------------------------------------
#define RSB 272                 // bytes per fp16 row (136 halves)
#define DS  136                 // D-stage row stride in halves (272 B)
#define H1SZ (TILE * RSB)       // 17408
#define SM_W2T    0             // 128 x 272 = 34816
#define SM_H1A    34816         // buf0; buf1 at 52224
#define SM_D      69632         // 64 x 272 = 17408 -> 87040
#define SM_SDST   87040         // 2 x 64 ints -> 87552
#define SM_TOTAL  87552

__global__ void __launch_bounds__(256, 2)
k_agg(const float* __restrict__ W2, const float* __restrict__ b2,
      int E, int ntiles)
{
    extern __shared__ char smem[];
    const unsigned sb = smem_u32(smem);
    const int t = threadIdx.x;
    const int lane = t & 31;
    const int wid = t >> 5;
    const int G = gridDim.x;

    // ---- one-time: W2^T (row j = output col, k contiguous) as fp16 ----
    {
        const int j = t >> 1, kh = t & 1;
        char* rowp = smem + SM_W2T + j * RSB + kh * 128;
#pragma unroll
        for (int v8 = 0; v8 < 8; v8++) {
            const int k0 = kh * 64 + 8 * v8;
            unsigned u[4];
#pragma unroll
            for (int m = 0; m < 4; m++)
                u[m] = pack_h2(W2[(k0 + 2 * m) * O + j],
                               W2[(k0 + 2 * m + 1) * O + j]);
            *(uint4*)(rowp + v8 * 16) = make_uint4(u[0], u[1], u[2], u[3]);
        }
    }

    int* sdst = (int*)(smem + SM_SDST);
    const int mr = wid & 1;              // m strip: rows 32*mr..+31
    const int nc = wid >> 1;             // n strip: cols 32*nc..+31
    const int e_g = t >> 2, q4 = t & 3;  // gather: edge, k-quarter
    const int jj = t & 127, sg = t >> 7; // walk: column, row-half
    const float b2j = b2[jj];

    const unsigned a_rel =
        (unsigned)((32 * mr + (lane & 7) + 8 * ((lane >> 3) & 1)) * RSB) +
        (unsigned)((lane >> 4) * 16);
    const unsigned b_base = sb + SM_W2T +
        (unsigned)((32 * nc + (lane & 7) + 8 * (lane >> 4)) * RSB) +
        (unsigned)(((lane >> 3) & 1) * 16);

    // ---- prologue: gather tile blockIdx.x directly into buf0 ----
    {
        const int cur = blockIdx.x;
        if (cur < ntiles) {
            const int eb = cur * TILE;
            const int ne = min(TILE, E - eb);
            if (e_g < ne) {
                const int2 ed = g_edge[eb + e_g];
                if (q4 == 0) sdst[e_g] = ed.y;
                const uint4* Ap = (const uint4*)(g_Ah + (size_t)ed.x * H + q4 * 32);
                const uint4* Bp = (const uint4*)(g_Bh + (size_t)ed.y * H + q4 * 32);
                char* rowp = smem + SM_H1A + e_g * RSB + q4 * 64;
#pragma unroll
                for (int i = 0; i < 4; i++) {
                    const uint4 a = Ap[i], b = Bp[i];
                    *(uint4*)(rowp + i * 16) =
                        make_uint4(srelu(a.x, b.x), srelu(a.y, b.y),
                                   srelu(a.z, b.z), srelu(a.w, b.w));
                }
            }
        }
    }
    __syncthreads();

    int it = 0;
    for (int cur = blockIdx.x; cur < ntiles; cur += G, it++) {
        const int par = it & 1;
        const int ne = min(TILE, E - cur * TILE);
        const int nxt = cur + G;

        // ---- prefetch LDGs for tile nxt (held in registers across MMA) ----
        uint4 pa[4], pb[4];
        int pdst = -1;
        bool have = false;
        if (nxt < ntiles) {
            const int eb2 = nxt * TILE;
            const int ne2 = min(TILE, E - eb2);
            if (e_g < ne2) {
                const int2 ed = g_edge[eb2 + e_g];
                pdst = ed.y;
                const uint4* Ap = (const uint4*)(g_Ah + (size_t)ed.x * H + q4 * 32);
                const uint4* Bp = (const uint4*)(g_Bh + (size_t)ed.y * H + q4 * 32);
#pragma unroll
                for (int i = 0; i < 4; i++) { pa[i] = Ap[i]; pb[i] = Bp[i]; }
                have = true;
            }
        }

        // ---- MMA: 32x32 per warp, fp16, 8 k16-steps, on buf par ----
        const unsigned a_base = sb + SM_H1A + (unsigned)(par * H1SZ) + a_rel;
        float acc[2][4][4];
#pragma unroll
        for (int f = 0; f < 2; f++)
#pragma unroll
            for (int nb = 0; nb < 4; nb++)
#pragma unroll
                for (int r = 0; r < 4; r++) acc[f][nb][r] = 0.0f;

#pragma unroll
        for (int ks = 0; ks < 8; ks++) {
            const unsigned off = (unsigned)(ks * 32);
            unsigned af0[4], af1[4], bp0[4], bp1[4];
            ldsm4(af0[0], af0[1], af0[2], af0[3], a_base + off);
            ldsm4(af1[0], af1[1], af1[2], af1[3], a_base + 16u * RSB + off);
            ldsm4(bp0[0], bp0[1], bp0[2], bp0[3], b_base + off);
            ldsm4(bp1[0], bp1[1], bp1[2], bp1[3], b_base + 16u * RSB + off);
            mma_f16(acc[0][0], af0, bp0[0], bp0[1]);
            mma_f16(acc[0][1], af0, bp0[2], bp0[3]);
            mma_f16(acc[0][2], af0, bp1[0], bp1[1]);
            mma_f16(acc[0][3], af0, bp1[2], bp1[3]);
            mma_f16(acc[1][0], af1, bp0[0], bp0[1]);
            mma_f16(acc[1][1], af1, bp0[2], bp0[3]);
            mma_f16(acc[1][2], af1, bp1[0], bp1[1]);
            mma_f16(acc[1][3], af1, bp1[2], bp1[3]);
        }

        // ---- stage D to smem as fp16 ----
        {
            const int r0 = 32 * mr + (lane >> 2);
            const int c0 = 32 * nc + 2 * (lane & 3);
#pragma unroll
            for (int f = 0; f < 2; f++)
#pragma unroll
                for (int nb = 0; nb < 4; nb++) {
                    const int r = r0 + 16 * f;
                    const int c = c0 + 8 * nb;
                    *(unsigned*)(smem + SM_D + r * (DS * 2) + c * 2) =
                        pack_h2(acc[f][nb][0], acc[f][nb][1]);
                    *(unsigned*)(smem + SM_D + (r + 8) * (DS * 2) + c * 2) =
                        pack_h2(acc[f][nb][2], acc[f][nb][3]);
                }
        }
        __syncthreads();

        // ---- column-walk segmented max (dst non-decreasing within tile) ----
        {
            const __half* Dh = (const __half*)(smem + SM_D);
            const int* sd = sdst + par * TILE;
            const int e0 = sg * 32;
            if (ne == TILE) {
                int seg = sd[e0];
                float mx = -__int_as_float(0x7f800000);
#pragma unroll
                for (int q = 0; q < 32; q++) {
                    const int e = e0 + q;
                    const float v = __half2float(Dh[e * DS + jj]);
                    const int dd = sd[e];
                    if (dd != seg) {
                        atomicMax(&g_enc[(size_t)seg * O + jj],
                                  fenc(mx + b2j) - ENC_OFF);
                        seg = dd;
                        mx = v;
                    } else {
                        mx = fmaxf(mx, v);
                    }
                }
                atomicMax(&g_enc[(size_t)seg * O + jj],
                          fenc(mx + b2j) - ENC_OFF);
            } else if (e0 < ne) {
                const int e1 = min(e0 + 32, ne);
                int seg = sd[e0];
                float mx = -__int_as_float(0x7f800000);
                for (int e = e0; e < e1; e++) {
                    const float v = __half2float(Dh[e * DS + jj]);
                    const int dd = sd[e];
                    if (dd != seg) {
                        atomicMax(&g_enc[(size_t)seg * O + jj],
                                  fenc(mx + b2j) - ENC_OFF);
                        seg = dd;
                        mx = v;
                    } else {
                        mx = fmaxf(mx, v);
                    }
                }
                atomicMax(&g_enc[(size_t)seg * O + jj],
                          fenc(mx + b2j) - ENC_OFF);
            }
        }

        // ---- convert + STS prefetched tile into buf par^1 ----
        if (have) {
            if (q4 == 0) sdst[(par ^ 1) * TILE + e_g] = pdst;
            char* rowp = smem + SM_H1A + (par ^ 1) * H1SZ + e_g * RSB + q4 * 64;
#pragma unroll
            for (int i = 0; i < 4; i++) {
                *(uint4*)(rowp + i * 16) =
                    make_uint4(srelu(pa[i].x, pb[i].x), srelu(pa[i].y, pb[i].y),
                               srelu(pa[i].z, pb[i].z), srelu(pa[i].w, pb[i].w));
            }
        }
        __syncthreads();
    }
}

// final: decode offset-encoded max (0 == empty -> 0.0), restore zeros so the
// next launch (graph replay) starts from a clean g_enc.
__global__ void k_decode(float* __restrict__ out, int NC)
{
    const int i = blockIdx.x * blockDim.x + threadIdx.x;
    if (i >= NC * O) return;
    const unsigned u = g_enc[i];
    out[i] = (u == 0u) ? 0.0f : fdec(u + ENC_OFF);
    g_enc[i] = 0u;
}

// ---------------------------------------------------------------------------
extern "C" void kernel_launch(void* const* d_in, const int* in_sizes, int n_in,
                              void* d_out, int out_size)
{
    const float* x     = (const float*)d_in[0];
    const float* pos   = (const float*)d_in[2];
    const float* pos_c = (const float*)d_in[3];
    const int*   src   = (const int*)d_in[4];
    const int*   dst   = (const int*)d_in[5];
    const float* W1    = (const float*)d_in[6];
    const float* b1    = (const float*)d_in[7];
    const float* W2    = (const float*)d_in[8];
    const float* b2    = (const float*)d_in[9];
    float* out = (float*)d_out;

    const int N  = in_sizes[0] / D;
    const int NC = in_sizes[1] / O;
    const int E  = in_sizes[4];
    const int ntiles = (E + TILE - 1) / TILE;
    const int nA = (N + 127) / 128;
    const int nB = (NC * H + 2047) / 2048;
    const int nH = 1600;
    const int nscan = (NC + 1023) / 1024;

    k_zero<<<nscan, 1024>>>(NC);
    k_pre<<<nA + nB + nH, 256>>>(x, pos, pos_c, W1, b1, dst,
                                 N, NC, E, nA, nB, nH);
    k_scan<<<nscan, 1024>>>(nscan, NC);
    k_scatter<<<(E + 255) / 256, 256>>>(src, dst, E);

    cudaFuncSetAttribute(k_agg, cudaFuncAttributeMaxDynamicSharedMemorySize,
                         SM_TOTAL);
    k_agg<<<304, 256, SM_TOTAL>>>(W2, b2, E, ntiles);
    k_decode<<<(NC * O + 255) / 256, 256>>>(out, NC);
}

// round 16
// speedup vs baseline: 1.0015x; 1.0015x over previous
#include <cuda_runtime.h>
#include <cuda_fp16.h>

// Problem constants (fixed by the dataset)
#define D   64
#define P   3
#define H   128
#define O   128
#define NMAX   100000
#define NCMAX  50000
#define EMAX   1600000
#define TILE   64

// ---------------- scratch (device globals; no allocation allowed) ----------
__device__ __half       g_Ah[NMAX * H];      // per-source layer-1 partial (+b1), fp16
__device__ __half       g_Bh[NCMAX * H];     // per-center layer-1 partial, fp16
__device__ int          g_rowptr[NCMAX + 1];
__device__ int          g_cursor[NCMAX];
__device__ int2         g_edge[EMAX];        // CSR-sorted (src, dst)
__device__ unsigned int g_enc[NCMAX * O];    // offset-encoded running max (0 = empty)
__device__ int          g_blocksum[64];      // scan partials
__device__ int          g_sflag[64];         // scan lookback flags

// ======================= helpers ===========================================
__device__ __forceinline__ unsigned smem_u32(const void* p) {
    unsigned a;
    asm("{ .reg .u64 t; cvta.to.shared.u64 t, %1; cvt.u32.u64 %0, t; }"
        : "=r"(a) : "l"(p));
    return a;
}
// order-preserving float->uint
__device__ __forceinline__ unsigned fenc(float f) {
    unsigned u = __float_as_uint(f);
    return (u & 0x80000000u) ? ~u : (u | 0x80000000u);
}
__device__ __forceinline__ float fdec(unsigned u) {
    return __uint_as_float((u & 0x80000000u) ? (u & 0x7fffffffu) : ~u);
}
// offset so that "empty" == 0 (g_enc is kept all-zero between launches)
#define ENC_OFF 0x007FFFFFu

__device__ __forceinline__ unsigned pack_h2(float lo, float hi) {
    unsigned u;
    asm("cvt.rn.f16x2.f32 %0, %1, %2;" : "=r"(u) : "f"(hi), "f"(lo));
    return u;
}
// relu(a - b) on packed half2
__device__ __forceinline__ unsigned srelu(unsigned au, unsigned bu) {
    __half2 a = *reinterpret_cast<__half2*>(&au);
    __half2 b = *reinterpret_cast<__half2*>(&bu);
    __half2 r = __hmax2(__hsub2(a, b), __float2half2_rn(0.0f));
    return *reinterpret_cast<unsigned*>(&r);
}
__device__ __forceinline__ void ldsm4(unsigned& r0, unsigned& r1,
                                      unsigned& r2, unsigned& r3, unsigned addr)
{
    asm volatile("ldmatrix.sync.aligned.m8n8.x4.shared.b16 {%0,%1,%2,%3}, [%4];"
                 : "=r"(r0), "=r"(r1), "=r"(r2), "=r"(r3) : "r"(addr));
}
__device__ __forceinline__ void mma_f16(float* d, const unsigned* a,
                                        unsigned b0, unsigned b1)
{
    asm volatile("mma.sync.aligned.m16n8k16.row.col.f32.f16.f16.f32 "
                 "{%0,%1,%2,%3}, {%4,%5,%6,%7}, {%8,%9}, {%0,%1,%2,%3};"
                 : "+f"(d[0]), "+f"(d[1]), "+f"(d[2]), "+f"(d[3])
                 : "r"(a[0]), "r"(a[1]), "r"(a[2]), "r"(a[3]),
                   "r"(b0), "r"(b1));
}

// ---------------------------------------------------------------------------
// k_zero: cursor + scan flags (g_enc maintained zero by k_decode)
// ---------------------------------------------------------------------------
__global__ void k_zero(int NC)
{
    const int i = blockIdx.x * 1024 + threadIdx.x;
    if (i < 64) { g_sflag[i] = 0; g_blocksum[i] = 0; }
    if (i < NC) g_cursor[i] = 0;
}

// ---------------------------------------------------------------------------
// k_pre (fused): block ranges
//   [0, nA)       : A = x@W1[:64] (fp16 MMA) + pos@W1row + b1 -> g_Ah
//   [nA, nA+nB)   : B rows -> g_Bh
//   [nA+nB, +nH)  : histogram of dst into g_cursor
// ---------------------------------------------------------------------------
#define XSTR 144                 // smem row stride bytes (odd multiple of 16)

__global__ void __launch_bounds__(256, 2)
k_pre(const float* __restrict__ x, const float* __restrict__ pos,
      const float* __restrict__ pos_c, const float* __restrict__ W1,
      const float* __restrict__ b1, const int* __restrict__ dst,
      int N, int NC, int E, int nA, int nB, int nH)
{
    const int t = threadIdx.x;
    const int bid = blockIdx.x;

    if (bid >= nA + nB) {               // histogram
        const int i0 = (bid - nA - nB) * 256 + t;
        const int stride = nH * 256;
        for (int e = i0; e < E; e += stride) atomicAdd(&g_cursor[dst[e]], 1);
        return;
    }
    if (bid >= nA) {                    // B rows
        const int bb = bid - nA;
#pragma unroll
        for (int r = 0; r < 8; r++) {
            const int idx = bb * 2048 + r * 256 + t;
            if (idx < NC * H) {
                const int c = idx >> 7;
                const int h = idx & 127;
                const float v = pos_c[c * 3 + 0] * W1[(D + 0) * H + h]
                              + pos_c[c * 3 + 1] * W1[(D + 1) * H + h]
                              + pos_c[c * 3 + 2] * W1[(D + 2) * H + h];
                g_Bh[idx] = __float2half_rn(v);
            }
        }
        return;
    }

    // ---- A-GEMM block ----
    __shared__ char xs_raw[128 * XSTR];     // x tile, fp16 [128 rows][64 k]
    __shared__ char w1_raw[128 * XSTR];     // W1^T,  fp16 [128 j][64 k]
    __shared__ float posS[128][4];
    __shared__ float w1r[3][128];
    __shared__ float b1s[128];

    const int lane = t & 31, wid = t >> 5;
    const int rbase = bid * 128;

    {
        const int r = t >> 1, kh = t & 1;
        const int row = rbase + r;
        char* rp = xs_raw + r * XSTR + kh * 64;
        if (row < N) {
            const float4* xp = (const float4*)(x + (size_t)row * D + kh * 32);
#pragma unroll
            for (int i = 0; i < 4; i++) {
                const float4 v0 = xp[2 * i];
                const float4 v1 = xp[2 * i + 1];
                *(uint4*)(rp + i * 16) = make_uint4(
                    pack_h2(v0.x, v0.y), pack_h2(v0.z, v0.w),
                    pack_h2(v1.x, v1.y), pack_h2(v1.z, v1.w));
            }
        } else {
#pragma unroll
            for (int i = 0; i < 4; i++)
                *(uint4*)(rp + i * 16) = make_uint4(0, 0, 0, 0);
        }
    }
    {
        const int j = t >> 1, kh = t & 1;
        char* rp = w1_raw + j * XSTR + kh * 64;
#pragma unroll
        for (int i = 0; i < 4; i++) {
            const int k0 = kh * 32 + i * 8;
            unsigned u[4];
#pragma unroll
            for (int m = 0; m < 4; m++)
                u[m] = pack_h2(W1[(k0 + 2 * m) * H + j],
                               W1[(k0 + 2 * m + 1) * H + j]);
            *(uint4*)(rp + i * 16) = make_uint4(u[0], u[1], u[2], u[3]);
        }
    }
    if (t < 128) {
        const int row = rbase + t;
#pragma unroll
        for (int p = 0; p < P; p++) {
            posS[t][p] = (row < N) ? pos[(size_t)row * P + p] : 0.0f;
            w1r[p][t] = W1[(D + p) * H + t];
        }
        b1s[t] = b1[t];
    }
    __syncthreads();

    const int mw = wid & 3, nw = wid >> 2;
    const unsigned a_base = smem_u32(xs_raw) +
        (unsigned)((32 * mw + (lane & 7) + 8 * ((lane >> 3) & 1)) * XSTR) +
        (unsigned)((lane >> 4) * 16);
    const unsigned b_base = smem_u32(w1_raw) +
        (unsigned)((64 * nw + (lane & 7) + 8 * (lane >> 4)) * XSTR) +
        (unsigned)(((lane >> 3) & 1) * 16);

    float acc[2][8][4];
#pragma unroll
    for (int f = 0; f < 2; f++)
#pragma unroll
        for (int nb = 0; nb < 8; nb++)
#pragma unroll
            for (int r = 0; r < 4; r++) acc[f][nb][r] = 0.0f;

#pragma unroll
    for (int ks = 0; ks < 4; ks++) {
        const unsigned off = (unsigned)(ks * 32);
        unsigned af0[4], af1[4];
        ldsm4(af0[0], af0[1], af0[2], af0[3], a_base + off);
        ldsm4(af1[0], af1[1], af1[2], af1[3], a_base + 16u * XSTR + off);
#pragma unroll
        for (int q = 0; q < 4; q++) {
            unsigned bp[4];
            ldsm4(bp[0], bp[1], bp[2], bp[3],
                  b_base + (unsigned)(q * 16 * XSTR) + off);
            mma_f16(acc[0][2 * q],     af0, bp[0], bp[1]);
            mma_f16(acc[0][2 * q + 1], af0, bp[2], bp[3]);
            mma_f16(acc[1][2 * q],     af1, bp[0], bp[1]);
            mma_f16(acc[1][2 * q + 1], af1, bp[2], bp[3]);
        }
    }

    const int r0 = 32 * mw + (lane >> 2);
    const int c0 = 64 * nw + 2 * (lane & 3);
#pragma unroll
    for (int nb = 0; nb < 8; nb++) {
        const int c = c0 + 8 * nb;
        const float wc00 = w1r[0][c], wc01 = w1r[1][c], wc02 = w1r[2][c];
        const float wc10 = w1r[0][c + 1], wc11 = w1r[1][c + 1], wc12 = w1r[2][c + 1];
        const float bb0 = b1s[c], bb1 = b1s[c + 1];
#pragma unroll
        for (int f = 0; f < 2; f++) {
            const int rA = r0 + 16 * f;
            const int rB = rA + 8;
            const float d0 = acc[f][nb][0] + bb0 +
                posS[rA][0] * wc00 + posS[rA][1] * wc01 + posS[rA][2] * wc02;
            const float d1 = acc[f][nb][1] + bb1 +
                posS[rA][0] * wc10 + posS[rA][1] * wc11 + posS[rA][2] * wc12;
            const float d2 = acc[f][nb][2] + bb0 +
                posS[rB][0] * wc00 + posS[rB][1] * wc01 + posS[rB][2] * wc02;
            const float d3 = acc[f][nb][3] + bb1 +
                posS[rB][0] * wc10 + posS[rB][1] * wc11 + posS[rB][2] * wc12;
            if (rbase + rA < N)
                *(unsigned*)((char*)g_Ah + ((size_t)(rbase + rA) * H + c) * 2) =
                    pack_h2(d0, d1);
            if (rbase + rB < N)
                *(unsigned*)((char*)g_Ah + ((size_t)(rbase + rB) * H + c) * 2) =
                    pack_h2(d2, d3);
        }
    }
}

// ---------------------------------------------------------------------------
// k_scan: single-pass exclusive scan with decoupled lookback.
// grid = nblk (<=49) blocks of 1024; all resident in one wave, each block
// waits only on predecessors -> no deadlock. Flags zeroed by k_zero.
// ---------------------------------------------------------------------------
__global__ void k_scan(int nblk, int NC)
{
    __shared__ int wsum[32];
    __shared__ int s_off;
    const int tid = threadIdx.x, lane = tid & 31, w = tid >> 5;
    const int bid = blockIdx.x;
    const int i = bid * 1024 + tid;
    const int v = (i < NC) ? g_cursor[i] : 0;
    int inc = v;
#pragma unroll
    for (int o = 1; o < 32; o <<= 1) {
        const int n = __shfl_up_sync(0xFFFFFFFFu, inc, o);
        if (lane >= o) inc += n;
    }
    if (lane == 31) wsum[w] = inc;
    __syncthreads();
    if (w == 0) {
        int xv = wsum[lane];
#pragma unroll
        for (int o = 1; o < 32; o <<= 1) {
            const int n = __shfl_up_sync(0xFFFFFFFFu, xv, o);
            if (lane >= o) xv += n;
        }
        wsum[lane] = xv;
    }
    __syncthreads();
    const int total = wsum[31];

    if (tid == 0) {
        g_blocksum[bid] = total;
        __threadfence();
        atomicExch(&g_sflag[bid], 1);
    }
    // lookback: warp 0 collects predecessor partials
    if (w == 0) {
        int sum = 0;
        if (lane < bid) {
            while (atomicAdd(&g_sflag[lane], 0) == 0) {}
            sum = atomicAdd(&g_blocksum[lane], 0);
        }
        if (lane + 32 < bid) {
            while (atomicAdd(&g_sflag[lane + 32], 0) == 0) {}
            sum += atomicAdd(&g_blocksum[lane + 32], 0);
        }
#pragma unroll
        for (int o = 16; o > 0; o >>= 1)
            sum += __shfl_xor_sync(0xFFFFFFFFu, sum, o);
        if (lane == 0) s_off = sum;
    }
    __syncthreads();

    const int excl = (w ? wsum[w - 1] : 0) + inc - v + s_off;
    if (i < NC) {
        g_rowptr[i] = excl;
        g_cursor[i] = excl;
    }
    if (bid == nblk - 1 && tid == 1023) g_rowptr[NC] = s_off + total;
}

__global__ void k_scatter(const int* __restrict__ src,
                          const int* __restrict__ dst, int E)
{
    const int i = blockIdx.x * blockDim.x + threadIdx.x;
    if (i < E) {
        const int d = dst[i];
        const int p = atomicAdd(&g_cursor[d], 1);
        g_edge[p] = make_int2(src[i], d);
    }
}

// ---------------------------------------------------------------------------
// Aggregate: TILE=64, 256 threads, 2 CTAs/SM (grid 304 = 2 x 152 SMs).
// Static interleaved tile assignment. Double-buffered h1; prefetch tile+G
// LDGs held in regs across MMA. Offset encoding (empty == 0).
// (Byte-identical structure to the 409.7us R14 kernel.)
// ---------------------------------------------------------------------------
#define RSB 272                 // bytes per fp16 row (136 halves)
#define DS  136                 // D-stage row stride in halves (272 B)
#define H1SZ (TILE * RSB)       // 17408
#define SM_W2T    0             // 128 x 272 = 34816
#define SM_H1A    34816         // buf0; buf1 at 52224
#define SM_D      69632         // 64 x 272 = 17408 -> 87040
#define SM_SDST   87040         // 2 x 64 ints -> 87552
#define SM_TOTAL  87552

__global__ void __launch_bounds__(256, 2)
k_agg(const float* __restrict__ W2, const float* __restrict__ b2,
      int E, int ntiles)
{
    extern __shared__ char smem[];
    const unsigned sb = smem_u32(smem);
    const int t = threadIdx.x;
    const int lane = t & 31;
    const int wid = t >> 5;
    const int G = gridDim.x;

    // ---- one-time: W2^T (row j = output col, k contiguous) as fp16 ----
    {
        const int j = t >> 1, kh = t & 1;
        char* rowp = smem + SM_W2T + j * RSB + kh * 128;
#pragma unroll
        for (int v8 = 0; v8 < 8; v8++) {
            const int k0 = kh * 64 + 8 * v8;
            unsigned u[4];
#pragma unroll
            for (int m = 0; m < 4; m++)
                u[m] = pack_h2(W2[(k0 + 2 * m) * O + j],
                               W2[(k0 + 2 * m + 1) * O + j]);
            *(uint4*)(rowp + v8 * 16) = make_uint4(u[0], u[1], u[2], u[3]);
        }
    }

    int* sdst = (int*)(smem + SM_SDST);
    const int mr = wid & 1;              // m strip: rows 32*mr..+31
    const int nc = wid >> 1;             // n strip: cols 32*nc..+31
    const int e_g = t >> 2, q4 = t & 3;  // gather: edge, k-quarter
    const int jj = t & 127, sg = t >> 7; // walk: column, row-half
    const float b2j = b2[jj];

    const unsigned a_rel =
        (unsigned)((32 * mr + (lane & 7) + 8 * ((lane >> 3) & 1)) * RSB) +
        (unsigned)((lane >> 4) * 16);
    const unsigned b_base = sb + SM_W2T +
        (unsigned)((32 * nc + (lane & 7) + 8 * (lane >> 4)) * RSB) +
        (unsigned)(((lane >> 3) & 1) * 16);

    // ---- prologue: gather tile blockIdx.x directly into buf0 ----
    {
        const int cur = blockIdx.x;
        if (cur < ntiles) {
            const int eb = cur * TILE;
            const int ne = min(TILE, E - eb);
            if (e_g < ne) {
                const int2 ed = g_edge[eb + e_g];
                if (q4 == 0) sdst[e_g] = ed.y;
                const uint4* Ap = (const uint4*)(g_Ah + (size_t)ed.x * H + q4 * 32);
                const uint4* Bp = (const uint4*)(g_Bh + (size_t)ed.y * H + q4 * 32);
                char* rowp = smem + SM_H1A + e_g * RSB + q4 * 64;
#pragma unroll
                for (int i = 0; i < 4; i++) {
                    const uint4 a = Ap[i], b = Bp[i];
                    *(uint4*)(rowp + i * 16) =
                        make_uint4(srelu(a.x, b.x), srelu(a.y, b.y),
                                   srelu(a.z, b.z), srelu(a.w, b.w));
                }
            }
        }
    }
    __syncthreads();

    int it = 0;
    for (int cur = blockIdx.x; cur < ntiles; cur += G, it++) {
        const int par = it & 1;
        const int ne = min(TILE, E - cur * TILE);
        const int nxt = cur + G;

        // ---- prefetch LDGs for tile nxt (held in registers across MMA) ----
        uint4 pa[4], pb[4];
        int pdst = -1;
        bool have = false;
        if (nxt < ntiles) {
            const int eb2 = nxt * TILE;
            const int ne2 = min(TILE, E - eb2);
            if (e_g < ne2) {
                const int2 ed = g_edge[eb2 + e_g];
                pdst = ed.y;
                const uint4* Ap = (const uint4*)(g_Ah + (size_t)ed.x * H + q4 * 32);
                const uint4* Bp = (const uint4*)(g_Bh + (size_t)ed.y * H + q4 * 32);
#pragma unroll
                for (int i = 0; i < 4; i++) { pa[i] = Ap[i]; pb[i] = Bp[i]; }
                have = true;
            }
        }

        // ---- MMA: 32x32 per warp, fp16, 8 k16-steps, on buf par ----
        const unsigned a_base = sb + SM_H1A + (unsigned)(par * H1SZ) + a_rel;
        float acc[2][4][4];
#pragma unroll
        for (int f = 0; f < 2; f++)
#pragma unroll
            for (int nb = 0; nb < 4; nb++)
#pragma unroll
                for (int r = 0; r < 4; r++) acc[f][nb][r] = 0.0f;

#pragma unroll
        for (int ks = 0; ks < 8; ks++) {
            const unsigned off = (unsigned)(ks * 32);
            unsigned af0[4], af1[4], bp0[4], bp1[4];
            ldsm4(af0[0], af0[1], af0[2], af0[3], a_base + off);
            ldsm4(af1[0], af1[1], af1[2], af1[3], a_base + 16u * RSB + off);
            ldsm4(bp0[0], bp0[1], bp0[2], bp0[3], b_base + off);
            ldsm4(bp1[0], bp1[1], bp1[2], bp1[3], b_base + 16u * RSB + off);
            mma_f16(acc[0][0], af0, bp0[0], bp0[1]);
            mma_f16(acc[0][1], af0, bp0[2], bp0[3]);
            mma_f16(acc[0][2], af0, bp1[0], bp1[1]);
            mma_f16(acc[0][3], af0, bp1[2], bp1[3]);
            mma_f16(acc[1][0], af1, bp0[0], bp0[1]);
            mma_f16(acc[1][1], af1, bp0[2], bp0[3]);
            mma_f16(acc[1][2], af1, bp1[0], bp1[1]);
            mma_f16(acc[1][3], af1, bp1[2], bp1[3]);
        }

        // ---- stage D to smem as fp16 ----
        {
            const int r0 = 32 * mr + (lane >> 2);
            const int c0 = 32 * nc + 2 * (lane & 3);
#pragma unroll
            for (int f = 0; f < 2; f++)
#pragma unroll
                for (int nb = 0; nb < 4; nb++) {
                    const int r = r0 + 16 * f;
                    const int c = c0 + 8 * nb;
                    *(unsigned*)(smem + SM_D + r * (DS * 2) + c * 2) =
                        pack_h2(acc[f][nb][0], acc[f][nb][1]);
                    *(unsigned*)(smem + SM_D + (r + 8) * (DS * 2) + c * 2) =
                        pack_h2(acc[f][nb][2], acc[f][nb][3]);
                }
        }
        __syncthreads();

        // ---- column-walk segmented max (dst non-decreasing within tile) ----
        {
            const __half* Dh = (const __half*)(smem + SM_D);
            const int* sd = sdst + par * TILE;
            const int e0 = sg * 32;
            if (ne == TILE) {
                int seg = sd[e0];
                float mx = -__int_as_float(0x7f800000);
#pragma unroll
                for (int q = 0; q < 32; q++) {
                    const int e = e0 + q;
                    const float v = __half2float(Dh[e * DS + jj]);
                    const int dd = sd[e];
                    if (dd != seg) {
                        atomicMax(&g_enc[(size_t)seg * O + jj],
                                  fenc(mx + b2j) - ENC_OFF);
                        seg = dd;
                        mx = v;
                    } else {
                        mx = fmaxf(mx, v);
                    }
                }
                atomicMax(&g_enc[(size_t)seg * O + jj],
                          fenc(mx + b2j) - ENC_OFF);
            } else if (e0 < ne) {
                const int e1 = min(e0 + 32, ne);
                int seg = sd[e0];
                float mx = -__int_as_float(0x7f800000);
                for (int e = e0; e < e1; e++) {
                    const float v = __half2float(Dh[e * DS + jj]);
                    const int dd = sd[e];
                    if (dd != seg) {
                        atomicMax(&g_enc[(size_t)seg * O + jj],
                                  fenc(mx + b2j) - ENC_OFF);
                        seg = dd;
                        mx = v;
                    } else {
                        mx = fmaxf(mx, v);
                    }
                }
                atomicMax(&g_enc[(size_t)seg * O + jj],
                          fenc(mx + b2j) - ENC_OFF);
            }
        }

        // ---- convert + STS prefetched tile into buf par^1 ----
        if (have) {
            if (q4 == 0) sdst[(par ^ 1) * TILE + e_g] = pdst;
            char* rowp = smem + SM_H1A + (par ^ 1) * H1SZ + e_g * RSB + q4 * 64;
#pragma unroll
            for (int i = 0; i < 4; i++) {
                *(uint4*)(rowp + i * 16) =
                    make_uint4(srelu(pa[i].x, pb[i].x), srelu(pa[i].y, pb[i].y),
                               srelu(pa[i].z, pb[i].z), srelu(pa[i].w, pb[i].w));
            }
        }
        __syncthreads();
    }
}

// final: decode offset-encoded max (0 == empty -> 0.0), restore zeros so the
// next launch (graph replay) starts from a clean g_enc.
__global__ void k_decode(float* __restrict__ out, int NC)
{
    const int i = blockIdx.x * blockDim.x + threadIdx.x;
    if (i >= NC * O) return;
    const unsigned u = g_enc[i];
    out[i] = (u == 0u) ? 0.0f : fdec(u + ENC_OFF);
    g_enc[i] = 0u;
}

// ---------------------------------------------------------------------------
extern "C" void kernel_launch(void* const* d_in, const int* in_sizes, int n_in,
                              void* d_out, int out_size)
{
    const float* x     = (const float*)d_in[0];
    const float* pos   = (const float*)d_in[2];
    const float* pos_c = (const float*)d_in[3];
    const int*   src   = (const int*)d_in[4];
    const int*   dst   = (const int*)d_in[5];
    const float* W1    = (const float*)d_in[6];
    const float* b1    = (const float*)d_in[7];
    const float* W2    = (const float*)d_in[8];
    const float* b2    = (const float*)d_in[9];
    float* out = (float*)d_out;

    const int N  = in_sizes[0] / D;
    const int NC = in_sizes[1] / O;
    const int E  = in_sizes[4];
    const int ntiles = (E + TILE - 1) / TILE;
    const int nA = (N + 127) / 128;
    const int nB = (NC * H + 2047) / 2048;
    const int nH = 1600;
    const int nscan = (NC + 1023) / 1024;

    k_zero<<<nscan, 1024>>>(NC);
    k_pre<<<nA + nB + nH, 256>>>(x, pos, pos_c, W1, b1, dst,
                                 N, NC, E, nA, nB, nH);
    k_scan<<<nscan, 1024>>>(nscan, NC);
    k_scatter<<<(E + 255) / 256, 256>>>(src, dst, E);

    cudaFuncSetAttribute(k_agg, cudaFuncAttributeMaxDynamicSharedMemorySize,
                         SM_TOTAL);
    k_agg<<<304, 256, SM_TOTAL>>>(W2, b2, E, ntiles);
    k_decode<<<(NC * O + 255) / 256, 256>>>(out, NC);
}

// round 17
// speedup vs baseline: 1.0534x; 1.0519x over previous
#include <cuda_runtime.h>
#include <cuda_fp16.h>

// Problem constants (fixed by the dataset)
#define D   64
#define P   3
#define H   128
#define O   128
#define NMAX   100000
#define NCMAX  50000
#define EMAX   1600000
#define TILE   64

// ---------------- scratch (device globals; no allocation allowed) ----------
__device__ __half       g_Ah[NMAX * H];      // per-source layer-1 partial (+b1), fp16
__device__ __half       g_Bh[NCMAX * H];     // per-center layer-1 partial, fp16
__device__ int          g_rowptr[NCMAX + 1];
__device__ int          g_cursor[NCMAX];
__device__ int2         g_edge[EMAX];        // CSR-sorted (src, dst)
__device__ unsigned int g_enc[NCMAX * O];    // offset-encoded running max (0 = empty)
__device__ int          g_tilectr;           // init path only
__device__ int          g_blocksum[64];      // scan partials

// ======================= helpers ===========================================
__device__ __forceinline__ unsigned smem_u32(const void* p) {
    unsigned a;
    asm("{ .reg .u64 t; cvta.to.shared.u64 t, %1; cvt.u32.u64 %0, t; }"
        : "=r"(a) : "l"(p));
    return a;
}
// order-preserving float->uint
__device__ __forceinline__ unsigned fenc(float f) {
    unsigned u = __float_as_uint(f);
    return (u & 0x80000000u) ? ~u : (u | 0x80000000u);
}
__device__ __forceinline__ float fdec(unsigned u) {
    return __uint_as_float((u & 0x80000000u) ? (u & 0x7fffffffu) : ~u);
}
// offset so that "empty" == 0 (g_enc is kept all-zero between launches)
#define ENC_OFF 0x007FFFFFu

__device__ __forceinline__ unsigned pack_h2(float lo, float hi) {
    unsigned u;
    asm("cvt.rn.f16x2.f32 %0, %1, %2;" : "=r"(u) : "f"(hi), "f"(lo));
    return u;
}
// relu(a - b) on packed half2
__device__ __forceinline__ unsigned srelu(unsigned au, unsigned bu) {
    __half2 a = *reinterpret_cast<__half2*>(&au);
    __half2 b = *reinterpret_cast<__half2*>(&bu);
    __half2 r = __hmax2(__hsub2(a, b), __float2half2_rn(0.0f));
    return *reinterpret_cast<unsigned*>(&r);
}
__device__ __forceinline__ void ldsm4(unsigned& r0, unsigned& r1,
                                      unsigned& r2, unsigned& r3, unsigned addr)
{
    asm volatile("ldmatrix.sync.aligned.m8n8.x4.shared.b16 {%0,%1,%2,%3}, [%4];"
                 : "=r"(r0), "=r"(r1), "=r"(r2), "=r"(r3) : "r"(addr));
}
__device__ __forceinline__ void mma_f16(float* d, const unsigned* a,
                                        unsigned b0, unsigned b1)
{
    asm volatile("mma.sync.aligned.m16n8k16.row.col.f32.f16.f16.f32 "
                 "{%0,%1,%2,%3}, {%4,%5,%6,%7}, {%8,%9}, {%0,%1,%2,%3};"
                 : "+f"(d[0]), "+f"(d[1]), "+f"(d[2]), "+f"(d[3])
                 : "r"(a[0]), "r"(a[1]), "r"(a[2]), "r"(a[3]),
                   "r"(b0), "r"(b1));
}

// ---------------------------------------------------------------------------
// k_preA: A = x @ W1[:64] (fp16 MMA, fp32 accum) + pos @ W1[64:67] + b1 (fp32
// epilogue), written to g_Ah as fp16. Blocks [0,nblkA): 128 nodes each.
// Blocks [nblkA, nblkA+NZ): zero g_cursor / g_tilectr.
// ---------------------------------------------------------------------------
#define XSTR 144                 // smem row stride bytes (odd multiple of 16)
#define NZ_BLOCKS 200

__global__ void __launch_bounds__(256, 2)
k_preA(const float* __restrict__ x, const float* __restrict__ pos,
       const float* __restrict__ W1, const float* __restrict__ b1,
       int N, int NC, int nblkA)
{
    const int t = threadIdx.x;
    const int bid = blockIdx.x;

    if (bid >= nblkA) {   // zero/init blocks
        const int zt = (bid - nblkA) * 256 + t;
        const int zstride = NZ_BLOCKS * 256;
        if (zt == 0) g_tilectr = 0;
        for (int i = zt; i < NC; i += zstride) g_cursor[i] = 0;
        return;
    }

    __shared__ char xs_raw[128 * XSTR];     // x tile, fp16 [128 rows][64 k]
    __shared__ char w1_raw[128 * XSTR];     // W1^T,  fp16 [128 j][64 k]
    __shared__ float posS[128][4];
    __shared__ float w1r[3][128];
    __shared__ float b1s[128];

    const int lane = t & 31, wid = t >> 5;
    const int rbase = bid * 128;

    // x -> fp16 smem (row, 32-col half per thread)
    {
        const int r = t >> 1, kh = t & 1;
        const int row = rbase + r;
        char* rp = xs_raw + r * XSTR + kh * 64;
        if (row < N) {
            const float4* xp = (const float4*)(x + (size_t)row * D + kh * 32);
#pragma unroll
            for (int i = 0; i < 4; i++) {
                const float4 v0 = xp[2 * i];
                const float4 v1 = xp[2 * i + 1];
                *(uint4*)(rp + i * 16) = make_uint4(
                    pack_h2(v0.x, v0.y), pack_h2(v0.z, v0.w),
                    pack_h2(v1.x, v1.y), pack_h2(v1.z, v1.w));
            }
        } else {
#pragma unroll
            for (int i = 0; i < 4; i++)
                *(uint4*)(rp + i * 16) = make_uint4(0, 0, 0, 0);
        }
    }
    // W1^T -> fp16 smem (j row, 32-k half per thread)
    {
        const int j = t >> 1, kh = t & 1;
        char* rp = w1_raw + j * XSTR + kh * 64;
#pragma unroll
        for (int i = 0; i < 4; i++) {
            const int k0 = kh * 32 + i * 8;
            unsigned u[4];
#pragma unroll
            for (int m = 0; m < 4; m++)
                u[m] = pack_h2(W1[(k0 + 2 * m) * H + j],
                               W1[(k0 + 2 * m + 1) * H + j]);
            *(uint4*)(rp + i * 16) = make_uint4(u[0], u[1], u[2], u[3]);
        }
    }
    if (t < 128) {
        const int row = rbase + t;
#pragma unroll
        for (int p = 0; p < P; p++) {
            posS[t][p] = (row < N) ? pos[(size_t)row * P + p] : 0.0f;
            w1r[p][t] = W1[(D + p) * H + t];
        }
        b1s[t] = b1[t];
    }
    __syncthreads();

    // MMA: 8 warps = 4(m) x 2(n); warp tile 32 rows x 64 cols; K=64
    const int mw = wid & 3, nw = wid >> 2;
    const unsigned a_base = smem_u32(xs_raw) +
        (unsigned)((32 * mw + (lane & 7) + 8 * ((lane >> 3) & 1)) * XSTR) +
        (unsigned)((lane >> 4) * 16);
    const unsigned b_base = smem_u32(w1_raw) +
        (unsigned)((64 * nw + (lane & 7) + 8 * (lane >> 4)) * XSTR) +
        (unsigned)(((lane >> 3) & 1) * 16);

    float acc[2][8][4];
#pragma unroll
    for (int f = 0; f < 2; f++)
#pragma unroll
        for (int nb = 0; nb < 8; nb++)
#pragma unroll
            for (int r = 0; r < 4; r++) acc[f][nb][r] = 0.0f;

#pragma unroll
    for (int ks = 0; ks < 4; ks++) {
        const unsigned off = (unsigned)(ks * 32);
        unsigned af0[4], af1[4];
        ldsm4(af0[0], af0[1], af0[2], af0[3], a_base + off);
        ldsm4(af1[0], af1[1], af1[2], af1[3], a_base + 16u * XSTR + off);
#pragma unroll
        for (int q = 0; q < 4; q++) {
            unsigned bp[4];
            ldsm4(bp[0], bp[1], bp[2], bp[3],
                  b_base + (unsigned)(q * 16 * XSTR) + off);
            mma_f16(acc[0][2 * q],     af0, bp[0], bp[1]);
            mma_f16(acc[0][2 * q + 1], af0, bp[2], bp[3]);
            mma_f16(acc[1][2 * q],     af1, bp[0], bp[1]);
            mma_f16(acc[1][2 * q + 1], af1, bp[2], bp[3]);
        }
    }

    // epilogue: + pos@W1row + b1, cvt fp16, store
    const int r0 = 32 * mw + (lane >> 2);
    const int c0 = 64 * nw + 2 * (lane & 3);
#pragma unroll
    for (int nb = 0; nb < 8; nb++) {
        const int c = c0 + 8 * nb;
        const float wc00 = w1r[0][c], wc01 = w1r[1][c], wc02 = w1r[2][c];
        const float wc10 = w1r[0][c + 1], wc11 = w1r[1][c + 1], wc12 = w1r[2][c + 1];
        const float bb0 = b1s[c], bb1 = b1s[c + 1];
#pragma unroll
        for (int f = 0; f < 2; f++) {
            const int rA = r0 + 16 * f;
            const int rB = rA + 8;
            const float d0 = acc[f][nb][0] + bb0 +
                posS[rA][0] * wc00 + posS[rA][1] * wc01 + posS[rA][2] * wc02;
            const float d1 = acc[f][nb][1] + bb1 +
                posS[rA][0] * wc10 + posS[rA][1] * wc11 + posS[rA][2] * wc12;
            const float d2 = acc[f][nb][2] + bb0 +
                posS[rB][0] * wc00 + posS[rB][1] * wc01 + posS[rB][2] * wc02;
            const float d3 = acc[f][nb][3] + bb1 +
                posS[rB][0] * wc10 + posS[rB][1] * wc11 + posS[rB][2] * wc12;
            if (rbase + rA < N)
                *(unsigned*)((char*)g_Ah + ((size_t)(rbase + rA) * H + c) * 2) =
                    pack_h2(d0, d1);
            if (rbase + rB < N)
                *(unsigned*)((char*)g_Ah + ((size_t)(rbase + rB) * H + c) * 2) =
                    pack_h2(d2, d3);
        }
    }
}

// ---------------------------------------------------------------------------
// k_preB: blocks [0,nB): B rows (fp16); blocks [nB,nB+nH): histogram chunk.
// ---------------------------------------------------------------------------
__global__ void k_preB(const float* __restrict__ pos_c,
                       const float* __restrict__ W1,
                       const int* __restrict__ dst,
                       int NC, int E, int nB)
{
    const int tid = threadIdx.x;
    const int bid = blockIdx.x;
    if (bid < nB) {
#pragma unroll
        for (int r = 0; r < 8; r++) {
            const int idx = bid * 1024 + r * 128 + tid;
            if (idx < NC * H) {
                const int c = idx >> 7;
                const int h = idx & 127;
                const float v = pos_c[c * 3 + 0] * W1[(D + 0) * H + h]
                              + pos_c[c * 3 + 1] * W1[(D + 1) * H + h]
                              + pos_c[c * 3 + 2] * W1[(D + 2) * H + h];
                g_Bh[idx] = __float2half_rn(v);
            }
        }
    } else {
        const int i = (bid - nB) * 128 + tid;
        const int stride = (gridDim.x - nB) * 128;
        for (int e = i; e < E; e += stride) atomicAdd(&g_cursor[dst[e]], 1);
    }
}

// scan phase 1: per-block exclusive scan + block partial
__global__ void k_scan_part(int NC)
{
    __shared__ int wsum[32];
    const int tid = threadIdx.x, lane = tid & 31, w = tid >> 5;
    const int i = blockIdx.x * 1024 + tid;
    const int v = (i < NC) ? g_cursor[i] : 0;
    int inc = v;
#pragma unroll
    for (int o = 1; o < 32; o <<= 1) {
        const int n = __shfl_up_sync(0xFFFFFFFFu, inc, o);
        if (lane >= o) inc += n;
    }
    if (lane == 31) wsum[w] = inc;
    __syncthreads();
    if (w == 0) {
        int xv = wsum[lane];
#pragma unroll
        for (int o = 1; o < 32; o <<= 1) {
            const int n = __shfl_up_sync(0xFFFFFFFFu, xv, o);
            if (lane >= o) xv += n;
        }
        wsum[lane] = xv;
    }
    __syncthreads();
    if (i < NC) g_rowptr[i] = (w ? wsum[w - 1] : 0) + inc - v;
    if (tid == 1023) g_blocksum[blockIdx.x] = wsum[31];
}

// scan phase 2: every block redundantly top-scans the <=64 partials, adds.
__global__ void k_scan_add(int nblk, int NC)
{
    __shared__ int s_off, s_tot;
    const int tid = threadIdx.x;
    if (tid < 32) {
        const int lane = tid;
        const int v0 = (lane < nblk) ? g_blocksum[lane] : 0;
        const int v1 = (lane + 32 < nblk) ? g_blocksum[lane + 32] : 0;
        int inc0 = v0;
#pragma unroll
        for (int o = 1; o < 32; o <<= 1) {
            const int n = __shfl_up_sync(0xFFFFFFFFu, inc0, o);
            if (lane >= o) inc0 += n;
        }
        const int tot0 = __shfl_sync(0xFFFFFFFFu, inc0, 31);
        int inc1 = v1;
#pragma unroll
        for (int o = 1; o < 32; o <<= 1) {
            const int n = __shfl_up_sync(0xFFFFFFFFu, inc1, o);
            if (lane >= o) inc1 += n;
        }
        inc1 += tot0;
        const int bid = (int)blockIdx.x;
        const int excl0 = inc0 - v0, excl1 = inc1 - v1;
        if (lane == (bid & 31)) s_off = (bid < 32) ? excl0 : excl1;
        if (lane == 31) s_tot = inc1;
    }
    __syncthreads();
    const int i = blockIdx.x * 1024 + tid;
    if (i < NC) {
        const int r = g_rowptr[i] + s_off;
        g_rowptr[i] = r;
        g_cursor[i] = r;
    }
    if (blockIdx.x == 0 && tid == 0) g_rowptr[NC] = s_tot;
}

__global__ void k_scatter(const int* __restrict__ src,
                          const int* __restrict__ dst, int E)
{
    const int i = blockIdx.x * blockDim.x + threadIdx.x;
    if (i < E) {
        const int d = dst[i];
        const int p = atomicAdd(&g_cursor[d], 1);
        g_edge[p] = make_int2(src[i], d);
    }
}

// ---------------------------------------------------------------------------
// Aggregate: TILE=64, 256 threads, 3 CTAs/SM (grid 456 = 3 x 152 SMs).
// Single h1 buffer (cross-CTA overlap replaces double-buffering); sdst
// double-buffered (tiny). 2 syncs/iter: post-stage sync orders all ldsm
// before the next tile's h1 STS. Prefetch LDGs held in regs across MMA.
// ---------------------------------------------------------------------------
#define RSB 272                 // bytes per fp16 row (136 halves)
#define DS  136                 // D-stage row stride in halves (272 B)
#define SM_W2T    0             // 128 x 272 = 34816
#define SM_H1     34816         // 64 x 272 = 17408 -> 52224
#define SM_D      52224         // 64 x 272 = 17408 -> 69632
#define SM_SDST   69632         // 2 x 64 ints -> 70144
#define SM_TOTAL  70144

__global__ void __launch_bounds__(256, 3)
k_agg(const float* __restrict__ W2, const float* __restrict__ b2,
      int E, int ntiles)
{
    extern __shared__ char smem[];
    const unsigned sb = smem_u32(smem);
    const int t = threadIdx.x;
    const int lane = t & 31;
    const int wid = t >> 5;
    const int G = gridDim.x;

    // ---- one-time: W2^T (row j = output col, k contiguous) as fp16 ----
    {
        const int j = t >> 1, kh = t & 1;
        char* rowp = smem + SM_W2T + j * RSB + kh * 128;
#pragma unroll
        for (int v8 = 0; v8 < 8; v8++) {
            const int k0 = kh * 64 + 8 * v8;
            unsigned u[4];
#pragma unroll
            for (int m = 0; m < 4; m++)
                u[m] = pack_h2(W2[(k0 + 2 * m) * O + j],
                               W2[(k0 + 2 * m + 1) * O + j]);
            *(uint4*)(rowp + v8 * 16) = make_uint4(u[0], u[1], u[2], u[3]);
        }
    }

    int* sdst = (int*)(smem + SM_SDST);
    const int mr = wid & 1;              // m strip: rows 32*mr..+31
    const int nc = wid >> 1;             // n strip: cols 32*nc..+31
    const int e_g = t >> 2, q4 = t & 3;  // gather: edge, k-quarter
    const int jj = t & 127, sg = t >> 7; // walk: column, row-half
    const float b2j = b2[jj];

    const unsigned a_base = sb + SM_H1 +
        (unsigned)((32 * mr + (lane & 7) + 8 * ((lane >> 3) & 1)) * RSB) +
        (unsigned)((lane >> 4) * 16);
    const unsigned b_base = sb + SM_W2T +
        (unsigned)((32 * nc + (lane & 7) + 8 * (lane >> 4)) * RSB) +
        (unsigned)(((lane >> 3) & 1) * 16);

    // ---- prologue: gather tile blockIdx.x into h1, sdst[0] ----
    {
        const int cur = blockIdx.x;
        if (cur < ntiles) {
            const int eb = cur * TILE;
            const int ne = min(TILE, E - eb);
            if (e_g < ne) {
                const int2 ed = g_edge[eb + e_g];
                if (q4 == 0) sdst[e_g] = ed.y;
                const uint4* Ap = (const uint4*)(g_Ah + (size_t)ed.x * H + q4 * 32);
                const uint4* Bp = (const uint4*)(g_Bh + (size_t)ed.y * H + q4 * 32);
                char* rowp = smem + SM_H1 + e_g * RSB + q4 * 64;
#pragma unroll
                for (int i = 0; i < 4; i++) {
                    const uint4 a = Ap[i], b = Bp[i];
                    *(uint4*)(rowp + i * 16) =
                        make_uint4(srelu(a.x, b.x), srelu(a.y, b.y),
                                   srelu(a.z, b.z), srelu(a.w, b.w));
                }
            }
        }
    }
    __syncthreads();

    int it = 0;
    for (int cur = blockIdx.x; cur < ntiles; cur += G, it++) {
        const int par = it & 1;
        const int ne = min(TILE, E - cur * TILE);
        const int nxt = cur + G;

        // ---- prefetch LDGs for tile nxt (held in registers across MMA) ----
        uint4 pa[4], pb[4];
        int pdst = -1;
        bool have = false;
        if (nxt < ntiles) {
            const int eb2 = nxt * TILE;
            const int ne2 = min(TILE, E - eb2);
            if (e_g < ne2) {
                const int2 ed = g_edge[eb2 + e_g];
                pdst = ed.y;
                const uint4* Ap = (const uint4*)(g_Ah + (size_t)ed.x * H + q4 * 32);
                const uint4* Bp = (const uint4*)(g_Bh + (size_t)ed.y * H + q4 * 32);
#pragma unroll
                for (int i = 0; i < 4; i++) { pa[i] = Ap[i]; pb[i] = Bp[i]; }
                have = true;
            }
        }

        // ---- MMA: 32x32 per warp, fp16, 8 k16-steps, on h1 ----
        float acc[2][4][4];
#pragma unroll
        for (int f = 0; f < 2; f++)
#pragma unroll
            for (int nb = 0; nb < 4; nb++)
#pragma unroll
                for (int r = 0; r < 4; r++) acc[f][nb][r] = 0.0f;

#pragma unroll
        for (int ks = 0; ks < 8; ks++) {
            const unsigned off = (unsigned)(ks * 32);
            unsigned af0[4], af1[4], bp0[4], bp1[4];
            ldsm4(af0[0], af0[1], af0[2], af0[3], a_base + off);
            ldsm4(af1[0], af1[1], af1[2], af1[3], a_base + 16u * RSB + off);
            ldsm4(bp0[0], bp0[1], bp0[2], bp0[3], b_base + off);
            ldsm4(bp1[0], bp1[1], bp1[2], bp1[3], b_base + 16u * RSB + off);
            mma_f16(acc[0][0], af0, bp0[0], bp0[1]);
            mma_f16(acc[0][1], af0, bp0[2], bp0[3]);
            mma_f16(acc[0][2], af0, bp1[0], bp1[1]);
            mma_f16(acc[0][3], af0, bp1[2], bp1[3]);
            mma_f16(acc[1][0], af1, bp0[0], bp0[1]);
            mma_f16(acc[1][1], af1, bp0[2], bp0[3]);
            mma_f16(acc[1][2], af1, bp1[0], bp1[1]);
            mma_f16(acc[1][3], af1, bp1[2], bp1[3]);
        }

        // ---- stage D to smem as fp16 ----
        {
            const int r0 = 32 * mr + (lane >> 2);
            const int c0 = 32 * nc + 2 * (lane & 3);
#pragma unroll
            for (int f = 0; f < 2; f++)
#pragma unroll
                for (int nb = 0; nb < 4; nb++) {
                    const int r = r0 + 16 * f;
                    const int c = c0 + 8 * nb;
                    *(unsigned*)(smem + SM_D + r * (DS * 2) + c * 2) =
                        pack_h2(acc[f][nb][0], acc[f][nb][1]);
                    *(unsigned*)(smem + SM_D + (r + 8) * (DS * 2) + c * 2) =
                        pack_h2(acc[f][nb][2], acc[f][nb][3]);
                }
        }
        __syncthreads();   // D staged AND all ldsm of h1 complete

        // ---- column-walk segmented max (dst non-decreasing within tile) ----
        {
            const __half* Dh = (const __half*)(smem + SM_D);
            const int* sd = sdst + par * TILE;
            const int e0 = sg * 32;
            if (ne == TILE) {
                int seg = sd[e0];
                float mx = -__int_as_float(0x7f800000);
#pragma unroll
                for (int q = 0; q < 32; q++) {
                    const int e = e0 + q;
                    const float v = __half2float(Dh[e * DS + jj]);
                    const int dd = sd[e];
                    if (dd != seg) {
                        atomicMax(&g_enc[(size_t)seg * O + jj],
                                  fenc(mx + b2j) - ENC_OFF);
                        seg = dd;
                        mx = v;
                    } else {
                        mx = fmaxf(mx, v);
                    }
                }
                atomicMax(&g_enc[(size_t)seg * O + jj],
                          fenc(mx + b2j) - ENC_OFF);
            } else if (e0 < ne) {
                const int e1 = min(e0 + 32, ne);
                int seg = sd[e0];
                float mx = -__int_as_float(0x7f800000);
                for (int e = e0; e < e1; e++) {
                    const float v = __half2float(Dh[e * DS + jj]);
                    const int dd = sd[e];
                    if (dd != seg) {
                        atomicMax(&g_enc[(size_t)seg * O + jj],
                                  fenc(mx + b2j) - ENC_OFF);
                        seg = dd;
                        mx = v;
                    } else {
                        mx = fmaxf(mx, v);
                    }
                }
                atomicMax(&g_enc[(size_t)seg * O + jj],
                          fenc(mx + b2j) - ENC_OFF);
            }
        }

        // ---- convert + STS prefetched tile into h1 (safe post-sync) ----
        if (have) {
            if (q4 == 0) sdst[(par ^ 1) * TILE + e_g] = pdst;
            char* rowp = smem + SM_H1 + e_g * RSB + q4 * 64;
#pragma unroll
            for (int i = 0; i < 4; i++) {
                *(uint4*)(rowp + i * 16) =
                    make_uint4(srelu(pa[i].x, pb[i].x), srelu(pa[i].y, pb[i].y),
                               srelu(pa[i].z, pb[i].z), srelu(pa[i].w, pb[i].w));
            }
        }
        __syncthreads();
    }
}

// final: decode offset-encoded max (0 == empty -> 0.0), restore zeros so the
// next launch (graph replay) starts from a clean g_enc.
__global__ void k_decode(float* __restrict__ out, int NC)
{
    const int i = blockIdx.x * blockDim.x + threadIdx.x;
    if (i >= NC * O) return;
    const unsigned u = g_enc[i];
    out[i] = (u == 0u) ? 0.0f : fdec(u + ENC_OFF);
    g_enc[i] = 0u;
}

// ---------------------------------------------------------------------------
extern "C" void kernel_launch(void* const* d_in, const int* in_sizes, int n_in,
                              void* d_out, int out_size)
{
    const float* x     = (const float*)d_in[0];
    const float* pos   = (const float*)d_in[2];
    const float* pos_c = (const float*)d_in[3];
    const int*   src   = (const int*)d_in[4];
    const int*   dst   = (const int*)d_in[5];
    const float* W1    = (const float*)d_in[6];
    const float* b1    = (const float*)d_in[7];
    const float* W2    = (const float*)d_in[8];
    const float* b2    = (const float*)d_in[9];
    float* out = (float*)d_out;

    const int N  = in_sizes[0] / D;
    const int NC = in_sizes[1] / O;
    const int E  = in_sizes[4];
    const int ntiles = (E + TILE - 1) / TILE;
    const int nblkA = (N + 127) / 128;
    const int nB = (NC * H + 1023) / 1024;
    const int nH = 6250;
    const int nscan = (NC + 1023) / 1024;

    k_preA<<<nblkA + NZ_BLOCKS, 256>>>(x, pos, W1, b1, N, NC, nblkA);
    k_preB<<<nB + nH, 128>>>(pos_c, W1, dst, NC, E, nB);
    k_scan_part<<<nscan, 1024>>>(NC);
    k_scan_add<<<nscan, 1024>>>(nscan, NC);
    k_scatter<<<(E + 255) / 256, 256>>>(src, dst, E);

    cudaFuncSetAttribute(k_agg, cudaFuncAttributeMaxDynamicSharedMemorySize,
                         SM_TOTAL);
    k_agg<<<456, 256, SM_TOTAL>>>(W2, b2, E, ntiles);
    k_decode<<<(NC * O + 255) / 256, 256>>>(out, NC);
}